// round 5
// baseline (speedup 1.0000x reference)
#include <cuda_runtime.h>

#define NTOK   8192      // T*B = 256*32
#define D      128
#define NEXP   9
#define MTILE  64

// Scratch (device globals — no allocation allowed)
__device__ int g_counts[NEXP];
__device__ int g_buckets[NEXP * NTOK];

__global__ void zero_counts_kernel() {
    if (threadIdx.x < NEXP) g_counts[threadIdx.x] = 0;
}

// positions is int32 on device (JAX x64 disabled downcasts the int64 array).
__global__ void scatter_kernel(const int* __restrict__ positions) {
    int i = blockIdx.x * blockDim.x + threadIdx.x;
    if (i >= NTOK) return;
    int p = positions[i];
    int r = (p < NEXP - 1) ? p : (NEXP - 1);
    r = max(r, 0);                    // defensive: keep in-bounds no matter what
    int slot = atomicAdd(&g_counts[r], 1);
    if (slot < NTOK) g_buckets[r * NTOK + slot] = i;
}

// Grouped GEMM: block = (expert e, M-tile). Y[m][n] = sum_k X[m][k] * W[e][k][n] + b[e][n]
// Ws: [128][128] fp32 (64KB), Xs transposed: [k=128][m=64] (32KB), idxs: 64 ints.
__global__ __launch_bounds__(256) void gemm_kernel(
    const float* __restrict__ X, const float* __restrict__ W,
    const float* __restrict__ Bv, float* __restrict__ Y)
{
    extern __shared__ float smem[];
    float* Ws = smem;                        // D*D floats
    float* Xs = smem + D * D;                // D*MTILE floats, layout [k][m]
    int*  idxs = (int*)(smem + D * D + D * MTILE);

    const int e    = blockIdx.x;
    const int tile = blockIdx.y;
    const int count = g_counts[e];
    const int m0g  = tile * MTILE;
    if (m0g >= count) return;
    const int mvalid = min(MTILE, count - m0g);

    const int tid = threadIdx.x;

    // 1. token indices for this tile
    if (tid < MTILE) {
        idxs[tid] = (tid < mvalid) ? g_buckets[e * NTOK + m0g + tid] : -1;
    }

    // 2. stage W[e] into shared (16384 floats -> 16 float4 per thread)
    {
        const float4* Wg  = (const float4*)(W + (size_t)e * D * D);
        float4* Ws4 = (float4*)Ws;
        #pragma unroll
        for (int i = 0; i < 16; i++)
            Ws4[tid + i * 256] = Wg[tid + i * 256];
    }
    __syncthreads();

    // 3. stage X rows, transposed into Xs[k][m]. 4 threads per token row.
    {
        const int m = tid >> 2;            // 0..63
        const int kb = (tid & 3) * 32;     // k chunk base
        const int t = idxs[m];
        if (t >= 0) {
            const float4* xr = (const float4*)(X + (size_t)t * D + kb);
            #pragma unroll
            for (int q = 0; q < 8; q++) {
                float4 v = xr[q];
                int k = kb + q * 4;
                Xs[(k + 0) * MTILE + m] = v.x;
                Xs[(k + 1) * MTILE + m] = v.y;
                Xs[(k + 2) * MTILE + m] = v.z;
                Xs[(k + 3) * MTILE + m] = v.w;
            }
        }
    }
    __syncthreads();

    // 4. compute: 16 (n) x 16 (m) thread grid; each thread 4 tokens x 8 outputs
    const int tx = tid & 15;     // n group
    const int ty = tid >> 4;     // m group
    const int n0 = tx * 8;
    const int m0 = ty * 4;

    float acc[4][8];
    #pragma unroll
    for (int i = 0; i < 4; i++)
        #pragma unroll
        for (int j = 0; j < 8; j++) acc[i][j] = 0.0f;

    #pragma unroll 4
    for (int k = 0; k < D; k++) {
        float4 xv = *(const float4*)&Xs[k * MTILE + m0];
        float4 w0 = *(const float4*)&Ws[k * D + n0];
        float4 w1 = *(const float4*)&Ws[k * D + n0 + 4];
        float xm[4] = {xv.x, xv.y, xv.z, xv.w};
        float wn[8] = {w0.x, w0.y, w0.z, w0.w, w1.x, w1.y, w1.z, w1.w};
        #pragma unroll
        for (int i = 0; i < 4; i++)
            #pragma unroll
            for (int j = 0; j < 8; j++)
                acc[i][j] = fmaf(xm[i], wn[j], acc[i][j]);
    }

    // 5. bias + store
    float4 b0 = *(const float4*)&Bv[e * D + n0];
    float4 b1 = *(const float4*)&Bv[e * D + n0 + 4];
    const float bb[8] = {b0.x, b0.y, b0.z, b0.w, b1.x, b1.y, b1.z, b1.w};

    #pragma unroll
    for (int i = 0; i < 4; i++) {
        int m = m0 + i;
        if (m < mvalid) {
            int t = idxs[m];
            float* yr = Y + (size_t)t * D + n0;
            float4 o0, o1;
            o0.x = acc[i][0] + bb[0]; o0.y = acc[i][1] + bb[1];
            o0.z = acc[i][2] + bb[2]; o0.w = acc[i][3] + bb[3];
            o1.x = acc[i][4] + bb[4]; o1.y = acc[i][5] + bb[5];
            o1.z = acc[i][6] + bb[6]; o1.w = acc[i][7] + bb[7];
            *(float4*)(yr)     = o0;
            *(float4*)(yr + 4) = o1;
        }
    }
}

static const int GEMM_SMEM = (D * D + D * MTILE) * 4 + MTILE * 4;  // 98560 B

extern "C" void kernel_launch(void* const* d_in, const int* in_sizes, int n_in,
                              void* d_out, int out_size) {
    const int*   positions = (const int*)d_in[0];
    const float* X  = (const float*)d_in[1];
    const float* W  = (const float*)d_in[2];
    const float* Bv = (const float*)d_in[3];
    float* Y = (float*)d_out;

    cudaFuncSetAttribute(gemm_kernel,
                         cudaFuncAttributeMaxDynamicSharedMemorySize, GEMM_SMEM);

    zero_counts_kernel<<<1, 32>>>();
    scatter_kernel<<<(NTOK + 255) / 256, 256>>>(positions);
    dim3 grid(NEXP, (NTOK + MTILE - 1) / MTILE);
    gemm_kernel<<<grid, 256, GEMM_SMEM>>>(X, W, Bv, Y);
}